// round 6
// baseline (speedup 1.0000x reference)
#include <cuda_runtime.h>
#include <cuda_fp16.h>
#include <cstdint>

// ============================================================================
// PiLinear: out = qz(qz(x) @ qz(W)^T + b), qz(v) = round(v/u)*u, u = (pi/2)/256
//
// Exact-integer path: i = round(x/u), j = round(w/u) exact in f16; f16 MMA
// with f32 accumulation computes S = sum(i*j) exactly. Epilogue reconstructs
// round(S*u)*u (+bias, requantize).
//
// R6 = R5 + register double-buffered LDSM fragments: the ldmatrix batch for
// micro-step ks+1 is issued before the 32 MMAs of step ks, hiding the ~30cy
// shared-memory result latency behind tensor work.
// ============================================================================

#define U_F   0.006135923151542565f   // (pi/2)/256
#define INVU_F 162.97466172610083f    // 512/pi

static constexpr int M_DIM = 8192;
static constexpr int N_DIM = 4096;
static constexpr int K_DIM = 4096;

static constexpr int BM = 128, BN = 256, BK = 64;
static constexpr int STAGES = 3;
static constexpr int KT = K_DIM / BK;                         // 64 k-tiles
static constexpr int A_STAGE_BYTES = BM * BK * 2;             // 16384
static constexpr int B_STAGE_BYTES = BN * BK * 2;             // 32768
static constexpr int STAGE_BYTES = A_STAGE_BYTES + B_STAGE_BYTES;  // 49152
static constexpr int SMEM_SIZE = STAGES * STAGE_BYTES;        // 147456

static constexpr int MTILES = M_DIM / BM;   // 64
static constexpr int NTILES = N_DIM / BN;   // 16

// Quantized f16-integer operand copies (scratch; no allocation allowed).
static __device__ __align__(128) __half g_A16[(size_t)M_DIM * K_DIM];
static __device__ __align__(128) __half g_B16[(size_t)N_DIM * K_DIM];

// ----------------------------------------------------------------------------
// PTX helpers
// ----------------------------------------------------------------------------
__device__ __forceinline__ uint32_t smem_u32(const void* p) {
    uint32_t a;
    asm("{ .reg .u64 t; cvta.to.shared.u64 t, %1; cvt.u32.u64 %0, t; }"
        : "=r"(a) : "l"(p));
    return a;
}

#define CP_ASYNC16(dst, src) \
    asm volatile("cp.async.cg.shared.global [%0], [%1], 16;" \
                 :: "r"(dst), "l"(src) : "memory")
#define CP_COMMIT() asm volatile("cp.async.commit_group;" ::: "memory")
#define CP_WAIT1()  asm volatile("cp.async.wait_group 1;"  ::: "memory")

#define LDSM4(r, addr) \
    asm volatile("ldmatrix.sync.aligned.m8n8.x4.shared.b16 {%0,%1,%2,%3}, [%4];" \
                 : "=r"((r)[0]), "=r"((r)[1]), "=r"((r)[2]), "=r"((r)[3]) \
                 : "r"(addr))

#define MMA16816(d, a, b0, b1) \
    asm volatile("mma.sync.aligned.m16n8k16.row.col.f32.f16.f16.f32 " \
                 "{%0,%1,%2,%3}, {%4,%5,%6,%7}, {%8,%9}, {%0,%1,%2,%3};" \
                 : "+f"((d)[0]), "+f"((d)[1]), "+f"((d)[2]), "+f"((d)[3]) \
                 : "r"((a)[0]), "r"((a)[1]), "r"((a)[2]), "r"((a)[3]), \
                   "r"(b0), "r"(b1))

// ----------------------------------------------------------------------------
// Quantize-to-f16 pack kernel (75% DRAM roofline; unchanged)
// ----------------------------------------------------------------------------
__global__ void __launch_bounds__(256) quant_kernel(const float* __restrict__ s,
                                                    __half* __restrict__ d) {
    const size_t i = ((size_t)blockIdx.x * 256 + threadIdx.x) * 8;
    const float4 v0 = *reinterpret_cast<const float4*>(s + i);
    const float4 v1 = *reinterpret_cast<const float4*>(s + i + 4);
    unsigned short h[8];
    h[0] = __half_as_ushort(__float2half_rn(rintf(__fdiv_rn(v0.x, U_F))));
    h[1] = __half_as_ushort(__float2half_rn(rintf(__fdiv_rn(v0.y, U_F))));
    h[2] = __half_as_ushort(__float2half_rn(rintf(__fdiv_rn(v0.z, U_F))));
    h[3] = __half_as_ushort(__float2half_rn(rintf(__fdiv_rn(v0.w, U_F))));
    h[4] = __half_as_ushort(__float2half_rn(rintf(__fdiv_rn(v1.x, U_F))));
    h[5] = __half_as_ushort(__float2half_rn(rintf(__fdiv_rn(v1.y, U_F))));
    h[6] = __half_as_ushort(__float2half_rn(rintf(__fdiv_rn(v1.z, U_F))));
    h[7] = __half_as_ushort(__float2half_rn(rintf(__fdiv_rn(v1.w, U_F))));
    uint4 p;
    p.x = (uint32_t)h[0] | ((uint32_t)h[1] << 16);
    p.y = (uint32_t)h[2] | ((uint32_t)h[3] << 16);
    p.z = (uint32_t)h[4] | ((uint32_t)h[5] << 16);
    p.w = (uint32_t)h[6] | ((uint32_t)h[7] << 16);
    *reinterpret_cast<uint4*>(d + i) = p;
}

// ----------------------------------------------------------------------------
// Stage loader: A 16KB (1024 x 16B), B 32KB (2048 x 16B), XOR-swizzled rows.
// ----------------------------------------------------------------------------
__device__ __forceinline__ void load_stage(uint32_t sbase, int mbase, int nbase,
                                           int kbase, int tid) {
#pragma unroll
    for (int i = 0; i < 4; i++) {
        const int c = tid + i * 256;
        const int row = c >> 3, col16 = c & 7;
        const uint32_t dst = sbase + row * 128 + ((col16 ^ (row & 7)) << 4);
        const void* src = g_A16 + (size_t)(mbase + row) * K_DIM + kbase + col16 * 8;
        CP_ASYNC16(dst, src);
    }
#pragma unroll
    for (int i = 0; i < 8; i++) {
        const int c = tid + i * 256;
        const int row = c >> 3, col16 = c & 7;
        const uint32_t dst = sbase + A_STAGE_BYTES + row * 128 + ((col16 ^ (row & 7)) << 4);
        const void* src = g_B16 + (size_t)(nbase + row) * K_DIM + kbase + col16 * 8;
        CP_ASYNC16(dst, src);
    }
}

// ----------------------------------------------------------------------------
// GEMM: 128x256x64 CTA tile, 3-stage cp.async pipeline, 8 warps (2M x 4N),
// warp tile 64x64 via mma.sync m16n8k16, register-double-buffered fragments,
// fused pi-quantize epilogue.
// ----------------------------------------------------------------------------
__global__ void __launch_bounds__(256, 1)
gemm_kernel(const float* __restrict__ bias, float* __restrict__ out) {
    extern __shared__ __align__(1024) char smem[];
    const uint32_t sbase = smem_u32(smem);
    const int tid = threadIdx.x;
    const int lane = tid & 31;
    const int w = tid >> 5;

    // banded rasterization: 8 m-tiles x 16 n-tiles per band (128 CTAs/band)
    const int bid = blockIdx.x;
    const int band = bid >> 7;
    const int rem = bid & 127;
    const int mt = band * 8 + (rem & 7);
    const int nt = rem >> 3;
    const int mbase = mt * BM, nbase = nt * BN;

    // prologue: fill STAGES-1 = 2 stages (k-tiles 0 and 1)
#pragma unroll
    for (int s = 0; s < STAGES - 1; s++) {
        load_stage(sbase + s * STAGE_BYTES, mbase, nbase, s * BK, tid);
        CP_COMMIT();
    }

    const int mwarp = w >> 2;        // 0..1 -> 64-row slices
    const int nwarp = w & 3;         // 0..3 -> 64-col slices
    const int x7 = lane & 7;

    // per-lane invariant smem byte offsets (relative to stage base)
    uint32_t aoff[4], boff[4];
#pragma unroll
    for (int mi = 0; mi < 4; mi++)
        aoff[mi] = (uint32_t)((mwarp * 64 + mi * 16 + (lane & 15)) << 7);
#pragma unroll
    for (int nb = 0; nb < 4; nb++)
        boff[nb] = (uint32_t)(A_STAGE_BYTES +
                   ((nwarp * 64 + nb * 16 + (lane & 7) + ((lane >> 4) << 3)) << 7));
    const int acol = lane >> 4;          // A: +8 in k for lanes 16-31
    const int bcol = (lane >> 3) & 1;    // B: +8 in k pattern

    float acc[4][8][4];
#pragma unroll
    for (int mi = 0; mi < 4; mi++)
#pragma unroll
        for (int nj = 0; nj < 8; nj++)
#pragma unroll
            for (int e = 0; e < 4; e++) acc[mi][nj][e] = 0.f;

    // rolling stage cursors
    int cmp_s = 0;
    int ld_s  = STAGES - 1;

    // double-buffered fragments
    uint32_t a[2][4][4], b[2][4][4];

    for (int kt = 0; kt < KT; kt++) {
        CP_WAIT1();
        __syncthreads();
        const int next = kt + STAGES - 1;
        if (next < KT) {
            load_stage(sbase + ld_s * STAGE_BYTES, mbase, nbase, next * BK, tid);
        }
        CP_COMMIT();
        ld_s = (ld_s + 1 == STAGES) ? 0 : ld_s + 1;

        const uint32_t st = sbase + cmp_s * STAGE_BYTES;
        cmp_s = (cmp_s + 1 == STAGES) ? 0 : cmp_s + 1;

        // prime fragments for ks = 0
#pragma unroll
        for (int nb = 0; nb < 4; nb++)
            LDSM4(b[0][nb], st + boff[nb] + ((uint32_t)(bcol ^ x7) << 4));
#pragma unroll
        for (int mi = 0; mi < 4; mi++)
            LDSM4(a[0][mi], st + aoff[mi] + ((uint32_t)(acol ^ x7) << 4));

#pragma unroll
        for (int ks = 0; ks < 4; ks++) {
            const int cur = ks & 1, nxt = cur ^ 1;
            if (ks < 3) {
                // prefetch fragments for ks+1 BEFORE consuming ks's
#pragma unroll
                for (int nb = 0; nb < 4; nb++)
                    LDSM4(b[nxt][nb], st + boff[nb] +
                          ((uint32_t)(((ks + 1) * 2 + bcol) ^ x7) << 4));
#pragma unroll
                for (int mi = 0; mi < 4; mi++)
                    LDSM4(a[nxt][mi], st + aoff[mi] +
                          ((uint32_t)(((ks + 1) * 2 + acol) ^ x7) << 4));
            }
#pragma unroll
            for (int mi = 0; mi < 4; mi++)
#pragma unroll
                for (int nj = 0; nj < 8; nj++)
                    MMA16816(acc[mi][nj], a[cur][mi],
                             b[cur][nj >> 1][(nj & 1) * 2],
                             b[cur][nj >> 1][(nj & 1) * 2 + 1]);
        }
    }

    // ---- epilogue: exact S -> qz(S*u) (+bias) -> qz -> GMEM ----
    const int row0 = mbase + mwarp * 64;
    const int col0 = nbase + nwarp * 64;
    const int tr = lane >> 2;
    const int tc = (lane & 3) * 2;
#pragma unroll
    for (int mi = 0; mi < 4; mi++) {
#pragma unroll
        for (int rr = 0; rr < 2; rr++) {
            const int row = row0 + mi * 16 + rr * 8 + tr;
            float* orow = out + (size_t)row * N_DIM + col0;
#pragma unroll
            for (int nj = 0; nj < 8; nj++) {
                const int c = nj * 8 + tc;
                float2 o;
#pragma unroll
                for (int e = 0; e < 2; e++) {
                    const float sv = acc[mi][nj][rr * 2 + e];        // exact int S
                    const float q  = rintf(__fmul_rn(sv, U_F));      // round(S*u)
                    const float cv = __fmul_rn(q, U_F);              // qz(dot)
                    const float tv = cv + __ldg(bias + col0 + c + e);// + bias
                    (&o.x)[e] = __fmul_rn(rintf(__fmul_rn(tv, INVU_F)), U_F);
                }
                *reinterpret_cast<float2*>(orow + c) = o;
            }
        }
    }
}

// ----------------------------------------------------------------------------
// Host launcher (graph-capturable: kernel launches only)
// ----------------------------------------------------------------------------
extern "C" void kernel_launch(void* const* d_in, const int* in_sizes, int n_in,
                              void* d_out, int out_size) {
    const float* x = (const float*)d_in[0];   // [8192, 4096]
    const float* wgt = (const float*)d_in[1]; // [4096, 4096]
    const float* b = (const float*)d_in[2];   // [4096]
    float* out = (float*)d_out;               // [8192, 4096]

    void* a16 = nullptr; void* b16 = nullptr;
    cudaGetSymbolAddress(&a16, g_A16);
    cudaGetSymbolAddress(&b16, g_B16);

    quant_kernel<<<(int)(((size_t)M_DIM * K_DIM / 8) / 256), 256>>>(x, (__half*)a16);
    quant_kernel<<<(int)(((size_t)N_DIM * K_DIM / 8) / 256), 256>>>(wgt, (__half*)b16);

    static bool attr_set = false;
    if (!attr_set) {
        cudaFuncSetAttribute(gemm_kernel,
                             cudaFuncAttributeMaxDynamicSharedMemorySize, SMEM_SIZE);
        attr_set = true;
    }
    gemm_kernel<<<MTILES * NTILES, 256, SMEM_SIZE>>>(b, out);
}

// round 7
// speedup vs baseline: 1.0479x; 1.0479x over previous
#include <cuda_runtime.h>
#include <cuda_fp16.h>
#include <cstdint>

// ============================================================================
// PiLinear: out = qz(qz(x) @ qz(W)^T + b), qz(v) = round(v/u)*u, u = (pi/2)/256
//
// Exact-integer path: i = round(x/u), j = round(w/u) exact in f16; f16 MMA
// with f32 accumulation computes S = sum(i*j) exactly. Epilogue reconstructs
// round(S*u)*u (+bias, requantize).
//
// R7: BK 64 -> 128, STAGES 3 -> 2 (same 192KB smem footprint class).
// Halves the __syncthreads / wait_group count (64 -> 32 iterations) -- with
// 1 CTA/SM every barrier drains the whole MMA pipe, measured ~10% overhead.
// Frag double-buffering dropped (R6 proved it neutral).
// ============================================================================

#define U_F   0.006135923151542565f   // (pi/2)/256
#define INVU_F 162.97466172610083f    // 512/pi

static constexpr int M_DIM = 8192;
static constexpr int N_DIM = 4096;
static constexpr int K_DIM = 4096;

static constexpr int BM = 128, BN = 256, BK = 128;
static constexpr int STAGES = 2;
static constexpr int KT = K_DIM / BK;                         // 32 k-tiles
static constexpr int A_STAGE_BYTES = BM * BK * 2;             // 32768
static constexpr int B_STAGE_BYTES = BN * BK * 2;             // 65536
static constexpr int STAGE_BYTES = A_STAGE_BYTES + B_STAGE_BYTES;  // 98304
static constexpr int SMEM_SIZE = STAGES * STAGE_BYTES;        // 196608

static constexpr int MTILES = M_DIM / BM;   // 64
static constexpr int NTILES = N_DIM / BN;   // 16

// Quantized f16-integer operand copies (scratch; no allocation allowed).
static __device__ __align__(128) __half g_A16[(size_t)M_DIM * K_DIM];
static __device__ __align__(128) __half g_B16[(size_t)N_DIM * K_DIM];

// ----------------------------------------------------------------------------
// PTX helpers
// ----------------------------------------------------------------------------
__device__ __forceinline__ uint32_t smem_u32(const void* p) {
    uint32_t a;
    asm("{ .reg .u64 t; cvta.to.shared.u64 t, %1; cvt.u32.u64 %0, t; }"
        : "=r"(a) : "l"(p));
    return a;
}

#define CP_ASYNC16(dst, src) \
    asm volatile("cp.async.cg.shared.global [%0], [%1], 16;" \
                 :: "r"(dst), "l"(src) : "memory")
#define CP_COMMIT() asm volatile("cp.async.commit_group;" ::: "memory")
#define CP_WAIT0()  asm volatile("cp.async.wait_group 0;"  ::: "memory")

#define LDSM4(r, addr) \
    asm volatile("ldmatrix.sync.aligned.m8n8.x4.shared.b16 {%0,%1,%2,%3}, [%4];" \
                 : "=r"((r)[0]), "=r"((r)[1]), "=r"((r)[2]), "=r"((r)[3]) \
                 : "r"(addr))

#define MMA16816(d, a, b0, b1) \
    asm volatile("mma.sync.aligned.m16n8k16.row.col.f32.f16.f16.f32 " \
                 "{%0,%1,%2,%3}, {%4,%5,%6,%7}, {%8,%9}, {%0,%1,%2,%3};" \
                 : "+f"((d)[0]), "+f"((d)[1]), "+f"((d)[2]), "+f"((d)[3]) \
                 : "r"((a)[0]), "r"((a)[1]), "r"((a)[2]), "r"((a)[3]), \
                   "r"(b0), "r"(b1))

// ----------------------------------------------------------------------------
// Quantize-to-f16 pack kernel (74% DRAM roofline; unchanged)
// ----------------------------------------------------------------------------
__global__ void __launch_bounds__(256) quant_kernel(const float* __restrict__ s,
                                                    __half* __restrict__ d) {
    const size_t i = ((size_t)blockIdx.x * 256 + threadIdx.x) * 8;
    const float4 v0 = *reinterpret_cast<const float4*>(s + i);
    const float4 v1 = *reinterpret_cast<const float4*>(s + i + 4);
    unsigned short h[8];
    h[0] = __half_as_ushort(__float2half_rn(rintf(__fdiv_rn(v0.x, U_F))));
    h[1] = __half_as_ushort(__float2half_rn(rintf(__fdiv_rn(v0.y, U_F))));
    h[2] = __half_as_ushort(__float2half_rn(rintf(__fdiv_rn(v0.z, U_F))));
    h[3] = __half_as_ushort(__float2half_rn(rintf(__fdiv_rn(v0.w, U_F))));
    h[4] = __half_as_ushort(__float2half_rn(rintf(__fdiv_rn(v1.x, U_F))));
    h[5] = __half_as_ushort(__float2half_rn(rintf(__fdiv_rn(v1.y, U_F))));
    h[6] = __half_as_ushort(__float2half_rn(rintf(__fdiv_rn(v1.z, U_F))));
    h[7] = __half_as_ushort(__float2half_rn(rintf(__fdiv_rn(v1.w, U_F))));
    uint4 p;
    p.x = (uint32_t)h[0] | ((uint32_t)h[1] << 16);
    p.y = (uint32_t)h[2] | ((uint32_t)h[3] << 16);
    p.z = (uint32_t)h[4] | ((uint32_t)h[5] << 16);
    p.w = (uint32_t)h[6] | ((uint32_t)h[7] << 16);
    *reinterpret_cast<uint4*>(d + i) = p;
}

// ----------------------------------------------------------------------------
// Stage loader. Rows are 256B (128 halves); 16 slots of 16B per row,
// swizzle: slot ^= (row & 15). Conflict-free for stores and x4 ldmatrix.
// A: 2048 chunks (8/thread), B: 4096 chunks (16/thread).
// ----------------------------------------------------------------------------
__device__ __forceinline__ void load_stage(uint32_t sbase, int mbase, int nbase,
                                           int kbase, int tid) {
#pragma unroll
    for (int i = 0; i < 8; i++) {
        const int c = tid + i * 256;
        const int row = c >> 4, col16 = c & 15;
        const uint32_t dst = sbase + row * 256 + ((col16 ^ (row & 15)) << 4);
        const void* src = g_A16 + (size_t)(mbase + row) * K_DIM + kbase + col16 * 8;
        CP_ASYNC16(dst, src);
    }
#pragma unroll
    for (int i = 0; i < 16; i++) {
        const int c = tid + i * 256;
        const int row = c >> 4, col16 = c & 15;
        const uint32_t dst = sbase + A_STAGE_BYTES + row * 256 + ((col16 ^ (row & 15)) << 4);
        const void* src = g_B16 + (size_t)(nbase + row) * K_DIM + kbase + col16 * 8;
        CP_ASYNC16(dst, src);
    }
}

// ----------------------------------------------------------------------------
// GEMM: 128x256x128 CTA tile, 2-stage cp.async pipeline, 8 warps (2M x 4N),
// warp tile 64x64 via mma.sync m16n8k16, fused pi-quantize epilogue.
// ----------------------------------------------------------------------------
__global__ void __launch_bounds__(256, 1)
gemm_kernel(const float* __restrict__ bias, float* __restrict__ out) {
    extern __shared__ __align__(1024) char smem[];
    const uint32_t sbase = smem_u32(smem);
    const int tid = threadIdx.x;
    const int lane = tid & 31;
    const int w = tid >> 5;

    // banded rasterization: 8 m-tiles x 16 n-tiles per band (128 CTAs/band)
    const int bid = blockIdx.x;
    const int band = bid >> 7;
    const int rem = bid & 127;
    const int mt = band * 8 + (rem & 7);
    const int nt = rem >> 3;
    const int mbase = mt * BM, nbase = nt * BN;

    // prologue: fill stage 0 (k-tile 0)
    load_stage(sbase, mbase, nbase, 0, tid);
    CP_COMMIT();

    const int mwarp = w >> 2;        // 0..1 -> 64-row slices
    const int nwarp = w & 3;         // 0..3 -> 64-col slices

    // per-lane invariant smem byte offsets (relative to stage base, 256B rows)
    const int x15a = lane & 15;                              // A row mod 16
    const int x15b = (lane & 7) | (((lane >> 4) & 1) << 3);  // B row mod 16
    uint32_t aoff[4], boff[4];
#pragma unroll
    for (int mi = 0; mi < 4; mi++)
        aoff[mi] = (uint32_t)((mwarp * 64 + mi * 16 + x15a) << 8);
#pragma unroll
    for (int nb = 0; nb < 4; nb++)
        boff[nb] = (uint32_t)(A_STAGE_BYTES + ((nwarp * 64 + nb * 16 + x15b) << 8));
    const int acol = lane >> 4;          // A: +8 halves for lanes 16-31
    const int bcol = (lane >> 3) & 1;    // B: +8 halves pattern

    float acc[4][8][4];
#pragma unroll
    for (int mi = 0; mi < 4; mi++)
#pragma unroll
        for (int nj = 0; nj < 8; nj++)
#pragma unroll
            for (int e = 0; e < 4; e++) acc[mi][nj][e] = 0.f;

    for (int kt = 0; kt < KT; kt++) {
        CP_WAIT0();
        __syncthreads();
        const int cur = kt & 1;
        if (kt + 1 < KT) {
            load_stage(sbase + (cur ^ 1) * STAGE_BYTES, mbase, nbase,
                       (kt + 1) * BK, tid);
        }
        CP_COMMIT();

        const uint32_t st = sbase + cur * STAGE_BYTES;
#pragma unroll
        for (int ks = 0; ks < 8; ks++) {
            uint32_t a[4][4], b[4][4];
#pragma unroll
            for (int nb = 0; nb < 4; nb++)
                LDSM4(b[nb], st + boff[nb] +
                      ((uint32_t)((ks * 2 + bcol) ^ x15b) << 4));
#pragma unroll
            for (int mi = 0; mi < 4; mi++)
                LDSM4(a[mi], st + aoff[mi] +
                      ((uint32_t)((ks * 2 + acol) ^ x15a) << 4));
#pragma unroll
            for (int mi = 0; mi < 4; mi++)
#pragma unroll
                for (int nj = 0; nj < 8; nj++)
                    MMA16816(acc[mi][nj], a[mi],
                             b[nj >> 1][(nj & 1) * 2], b[nj >> 1][(nj & 1) * 2 + 1]);
        }
    }

    // ---- epilogue: exact S -> qz(S*u) (+bias) -> qz -> GMEM ----
    const int row0 = mbase + mwarp * 64;
    const int col0 = nbase + nwarp * 64;
    const int tr = lane >> 2;
    const int tc = (lane & 3) * 2;

    // prefetch the 16 bias values this lane needs (k-loop invariant)
    float bv[16];
#pragma unroll
    for (int nj = 0; nj < 8; nj++) {
        bv[nj * 2]     = __ldg(bias + col0 + nj * 8 + tc);
        bv[nj * 2 + 1] = __ldg(bias + col0 + nj * 8 + tc + 1);
    }

#pragma unroll
    for (int mi = 0; mi < 4; mi++) {
#pragma unroll
        for (int rr = 0; rr < 2; rr++) {
            const int row = row0 + mi * 16 + rr * 8 + tr;
            float* orow = out + (size_t)row * N_DIM + col0;
#pragma unroll
            for (int nj = 0; nj < 8; nj++) {
                const int c = nj * 8 + tc;
                float2 o;
#pragma unroll
                for (int e = 0; e < 2; e++) {
                    const float sv = acc[mi][nj][rr * 2 + e];        // exact int S
                    const float q  = rintf(__fmul_rn(sv, U_F));      // round(S*u)
                    const float cv = __fmul_rn(q, U_F);              // qz(dot)
                    const float tv = cv + bv[nj * 2 + e];            // + bias
                    (&o.x)[e] = __fmul_rn(rintf(__fmul_rn(tv, INVU_F)), U_F);
                }
                *reinterpret_cast<float2*>(orow + c) = o;
            }
        }
    }
}

// ----------------------------------------------------------------------------
// Host launcher (graph-capturable: kernel launches only)
// ----------------------------------------------------------------------------
extern "C" void kernel_launch(void* const* d_in, const int* in_sizes, int n_in,
                              void* d_out, int out_size) {
    const float* x = (const float*)d_in[0];   // [8192, 4096]
    const float* wgt = (const float*)d_in[1]; // [4096, 4096]
    const float* b = (const float*)d_in[2];   // [4096]
    float* out = (float*)d_out;               // [8192, 4096]

    void* a16 = nullptr; void* b16 = nullptr;
    cudaGetSymbolAddress(&a16, g_A16);
    cudaGetSymbolAddress(&b16, g_B16);

    quant_kernel<<<(int)(((size_t)M_DIM * K_DIM / 8) / 256), 256>>>(x, (__half*)a16);
    quant_kernel<<<(int)(((size_t)N_DIM * K_DIM / 8) / 256), 256>>>(wgt, (__half*)b16);

    static bool attr_set = false;
    if (!attr_set) {
        cudaFuncSetAttribute(gemm_kernel,
                             cudaFuncAttributeMaxDynamicSharedMemorySize, SMEM_SIZE);
        attr_set = true;
    }
    gemm_kernel<<<MTILES * NTILES, 256, SMEM_SIZE>>>(b, out);
}

// round 8
// speedup vs baseline: 1.0676x; 1.0188x over previous
#include <cuda_runtime.h>
#include <cuda_fp16.h>
#include <cstdint>

// ============================================================================
// PiLinear: out = qz(qz(x) @ qz(W)^T + b), qz(v) = round(v/u)*u, u = (pi/2)/256
//
// Exact-integer path: i = round(x/u), j = round(w/u) exact in f16; f16 MMA
// with f32 accumulation computes S = sum(i*j) exactly. Epilogue reconstructs
// round(S*u)*u (+bias, requantize).
//
// R8 = R7 + (a) next-stage cp.async burst moved AFTER the first ks micro-step
// so the 24-LDGSTS issue burst drains under tensor work instead of delaying
// the first LDSM/MMA; (b) the two quant launches merged into one kernel.
// ============================================================================

#define U_F   0.006135923151542565f   // (pi/2)/256
#define INVU_F 162.97466172610083f    // 512/pi

static constexpr int M_DIM = 8192;
static constexpr int N_DIM = 4096;
static constexpr int K_DIM = 4096;

static constexpr int BM = 128, BN = 256, BK = 128;
static constexpr int KT = K_DIM / BK;                         // 32 k-tiles
static constexpr int A_STAGE_BYTES = BM * BK * 2;             // 32768
static constexpr int B_STAGE_BYTES = BN * BK * 2;             // 65536
static constexpr int STAGE_BYTES = A_STAGE_BYTES + B_STAGE_BYTES;  // 98304
static constexpr int SMEM_SIZE = 2 * STAGE_BYTES;             // 196608

static constexpr int MTILES = M_DIM / BM;   // 64
static constexpr int NTILES = N_DIM / BN;   // 16

// Quantized f16-integer operand copies (scratch; no allocation allowed).
static __device__ __align__(128) __half g_A16[(size_t)M_DIM * K_DIM];
static __device__ __align__(128) __half g_B16[(size_t)N_DIM * K_DIM];

// ----------------------------------------------------------------------------
// PTX helpers
// ----------------------------------------------------------------------------
__device__ __forceinline__ uint32_t smem_u32(const void* p) {
    uint32_t a;
    asm("{ .reg .u64 t; cvta.to.shared.u64 t, %1; cvt.u32.u64 %0, t; }"
        : "=r"(a) : "l"(p));
    return a;
}

#define CP_ASYNC16(dst, src) \
    asm volatile("cp.async.cg.shared.global [%0], [%1], 16;" \
                 :: "r"(dst), "l"(src) : "memory")
#define CP_COMMIT() asm volatile("cp.async.commit_group;" ::: "memory")
#define CP_WAIT0()  asm volatile("cp.async.wait_group 0;"  ::: "memory")

#define LDSM4(r, addr) \
    asm volatile("ldmatrix.sync.aligned.m8n8.x4.shared.b16 {%0,%1,%2,%3}, [%4];" \
                 : "=r"((r)[0]), "=r"((r)[1]), "=r"((r)[2]), "=r"((r)[3]) \
                 : "r"(addr))

#define MMA16816(d, a, b0, b1) \
    asm volatile("mma.sync.aligned.m16n8k16.row.col.f32.f16.f16.f32 " \
                 "{%0,%1,%2,%3}, {%4,%5,%6,%7}, {%8,%9}, {%0,%1,%2,%3};" \
                 : "+f"((d)[0]), "+f"((d)[1]), "+f"((d)[2]), "+f"((d)[3]) \
                 : "r"((a)[0]), "r"((a)[1]), "r"((a)[2]), "r"((a)[3]), \
                   "r"(b0), "r"(b1))

// ----------------------------------------------------------------------------
// Merged quantize-to-f16 kernel: handles both x->A16 and w->B16 in one grid.
// x: 8192x4096 -> 16384 blocks; w: 4096x4096 -> 8192 blocks. 8 elems/thread.
// ----------------------------------------------------------------------------
static constexpr int XBLKS = (int)(((size_t)M_DIM * K_DIM / 8) / 256);  // 16384
static constexpr int WBLKS = (int)(((size_t)N_DIM * K_DIM / 8) / 256);  // 8192

__global__ void __launch_bounds__(256) quant2_kernel(
    const float* __restrict__ x, __half* __restrict__ a,
    const float* __restrict__ wgt, __half* __restrict__ b) {
    const int bid = blockIdx.x;
    const float* s;
    __half* d;
    size_t base;
    if (bid < XBLKS) { s = x;   d = a; base = (size_t)bid * 2048; }
    else             { s = wgt; d = b; base = (size_t)(bid - XBLKS) * 2048; }
    const size_t i = base + (size_t)threadIdx.x * 8;
    const float4 v0 = *reinterpret_cast<const float4*>(s + i);
    const float4 v1 = *reinterpret_cast<const float4*>(s + i + 4);
    unsigned short h[8];
    h[0] = __half_as_ushort(__float2half_rn(rintf(__fdiv_rn(v0.x, U_F))));
    h[1] = __half_as_ushort(__float2half_rn(rintf(__fdiv_rn(v0.y, U_F))));
    h[2] = __half_as_ushort(__float2half_rn(rintf(__fdiv_rn(v0.z, U_F))));
    h[3] = __half_as_ushort(__float2half_rn(rintf(__fdiv_rn(v0.w, U_F))));
    h[4] = __half_as_ushort(__float2half_rn(rintf(__fdiv_rn(v1.x, U_F))));
    h[5] = __half_as_ushort(__float2half_rn(rintf(__fdiv_rn(v1.y, U_F))));
    h[6] = __half_as_ushort(__float2half_rn(rintf(__fdiv_rn(v1.z, U_F))));
    h[7] = __half_as_ushort(__float2half_rn(rintf(__fdiv_rn(v1.w, U_F))));
    uint4 p;
    p.x = (uint32_t)h[0] | ((uint32_t)h[1] << 16);
    p.y = (uint32_t)h[2] | ((uint32_t)h[3] << 16);
    p.z = (uint32_t)h[4] | ((uint32_t)h[5] << 16);
    p.w = (uint32_t)h[6] | ((uint32_t)h[7] << 16);
    *reinterpret_cast<uint4*>(d + i) = p;
}

// ----------------------------------------------------------------------------
// Stage loader. Rows are 256B (128 halves); 16 slots of 16B per row,
// swizzle: slot ^= (row & 15). Conflict-free for stores and x4 ldmatrix.
// ----------------------------------------------------------------------------
__device__ __forceinline__ void load_stage(uint32_t sbase, int mbase, int nbase,
                                           int kbase, int tid) {
#pragma unroll
    for (int i = 0; i < 8; i++) {
        const int c = tid + i * 256;
        const int row = c >> 4, col16 = c & 15;
        const uint32_t dst = sbase + row * 256 + ((col16 ^ (row & 15)) << 4);
        const void* src = g_A16 + (size_t)(mbase + row) * K_DIM + kbase + col16 * 8;
        CP_ASYNC16(dst, src);
    }
#pragma unroll
    for (int i = 0; i < 16; i++) {
        const int c = tid + i * 256;
        const int row = c >> 4, col16 = c & 15;
        const uint32_t dst = sbase + A_STAGE_BYTES + row * 256 + ((col16 ^ (row & 15)) << 4);
        const void* src = g_B16 + (size_t)(nbase + row) * K_DIM + kbase + col16 * 8;
        CP_ASYNC16(dst, src);
    }
}

// ----------------------------------------------------------------------------
// GEMM: 128x256x128 CTA tile, 2-stage cp.async pipeline, 8 warps (2M x 4N),
// warp tile 64x64 via mma.sync m16n8k16, fused pi-quantize epilogue.
// Next-stage loads issued after the first ks micro-step.
// ----------------------------------------------------------------------------
__global__ void __launch_bounds__(256, 1)
gemm_kernel(const float* __restrict__ bias, float* __restrict__ out) {
    extern __shared__ __align__(1024) char smem[];
    const uint32_t sbase = smem_u32(smem);
    const int tid = threadIdx.x;
    const int lane = tid & 31;
    const int w = tid >> 5;

    // banded rasterization: 8 m-tiles x 16 n-tiles per band (128 CTAs/band)
    const int bid = blockIdx.x;
    const int band = bid >> 7;
    const int rem = bid & 127;
    const int mt = band * 8 + (rem & 7);
    const int nt = rem >> 3;
    const int mbase = mt * BM, nbase = nt * BN;

    // prologue: fill stage 0 (k-tile 0)
    load_stage(sbase, mbase, nbase, 0, tid);
    CP_COMMIT();

    const int mwarp = w >> 2;        // 0..1 -> 64-row slices
    const int nwarp = w & 3;         // 0..3 -> 64-col slices

    // per-lane invariant smem byte offsets (relative to stage base, 256B rows)
    const int x15a = lane & 15;                              // A row mod 16
    const int x15b = (lane & 7) | (((lane >> 4) & 1) << 3);  // B row mod 16
    uint32_t aoff[4], boff[4];
#pragma unroll
    for (int mi = 0; mi < 4; mi++)
        aoff[mi] = (uint32_t)((mwarp * 64 + mi * 16 + x15a) << 8);
#pragma unroll
    for (int nb = 0; nb < 4; nb++)
        boff[nb] = (uint32_t)(A_STAGE_BYTES + ((nwarp * 64 + nb * 16 + x15b) << 8));
    const int acol = lane >> 4;          // A: +8 halves for lanes 16-31
    const int bcol = (lane >> 3) & 1;    // B: +8 halves pattern

    float acc[4][8][4];
#pragma unroll
    for (int mi = 0; mi < 4; mi++)
#pragma unroll
        for (int nj = 0; nj < 8; nj++)
#pragma unroll
            for (int e = 0; e < 4; e++) acc[mi][nj][e] = 0.f;

    for (int kt = 0; kt < KT; kt++) {
        CP_WAIT0();
        __syncthreads();
        const int cur = kt & 1;
        const uint32_t st = sbase + cur * STAGE_BYTES;
#pragma unroll
        for (int ks = 0; ks < 8; ks++) {
            uint32_t a[4][4], b[4][4];
#pragma unroll
            for (int nb = 0; nb < 4; nb++)
                LDSM4(b[nb], st + boff[nb] +
                      ((uint32_t)((ks * 2 + bcol) ^ x15b) << 4));
#pragma unroll
            for (int mi = 0; mi < 4; mi++)
                LDSM4(a[mi], st + aoff[mi] +
                      ((uint32_t)((ks * 2 + acol) ^ x15a) << 4));
#pragma unroll
            for (int mi = 0; mi < 4; mi++)
#pragma unroll
                for (int nj = 0; nj < 8; nj++)
                    MMA16816(acc[mi][nj], a[mi],
                             b[nj >> 1][(nj & 1) * 2], b[nj >> 1][(nj & 1) * 2 + 1]);
            if (ks == 0) {
                // issue next-stage loads AFTER the first MMA block: the
                // 24-LDGSTS issue burst drains while the tensor pipe is busy.
                if (kt + 1 < KT) {
                    load_stage(sbase + (cur ^ 1) * STAGE_BYTES, mbase, nbase,
                               (kt + 1) * BK, tid);
                    CP_COMMIT();
                }
            }
        }
    }

    // ---- epilogue: exact S -> qz(S*u) (+bias) -> qz -> GMEM ----
    const int row0 = mbase + mwarp * 64;
    const int col0 = nbase + nwarp * 64;
    const int tr = lane >> 2;
    const int tc = (lane & 3) * 2;

    // prefetch the 16 bias values this lane needs
    float bv[16];
#pragma unroll
    for (int nj = 0; nj < 8; nj++) {
        bv[nj * 2]     = __ldg(bias + col0 + nj * 8 + tc);
        bv[nj * 2 + 1] = __ldg(bias + col0 + nj * 8 + tc + 1);
    }

#pragma unroll
    for (int mi = 0; mi < 4; mi++) {
#pragma unroll
        for (int rr = 0; rr < 2; rr++) {
            const int row = row0 + mi * 16 + rr * 8 + tr;
            float* orow = out + (size_t)row * N_DIM + col0;
#pragma unroll
            for (int nj = 0; nj < 8; nj++) {
                const int c = nj * 8 + tc;
                float2 o;
#pragma unroll
                for (int e = 0; e < 2; e++) {
                    const float sv = acc[mi][nj][rr * 2 + e];        // exact int S
                    const float q  = rintf(__fmul_rn(sv, U_F));      // round(S*u)
                    const float cv = __fmul_rn(q, U_F);              // qz(dot)
                    const float tv = cv + bv[nj * 2 + e];            // + bias
                    (&o.x)[e] = __fmul_rn(rintf(__fmul_rn(tv, INVU_F)), U_F);
                }
                *reinterpret_cast<float2*>(orow + c) = o;
            }
        }
    }
}

// ----------------------------------------------------------------------------
// Host launcher (graph-capturable: kernel launches only)
// ----------------------------------------------------------------------------
extern "C" void kernel_launch(void* const* d_in, const int* in_sizes, int n_in,
                              void* d_out, int out_size) {
    const float* x = (const float*)d_in[0];   // [8192, 4096]
    const float* wgt = (const float*)d_in[1]; // [4096, 4096]
    const float* b = (const float*)d_in[2];   // [4096]
    float* out = (float*)d_out;               // [8192, 4096]

    void* a16 = nullptr; void* b16 = nullptr;
    cudaGetSymbolAddress(&a16, g_A16);
    cudaGetSymbolAddress(&b16, g_B16);

    // quantize both operands in one launch
    quant2_kernel<<<XBLKS + WBLKS, 256>>>(x, (__half*)a16, wgt, (__half*)b16);

    static bool attr_set = false;
    if (!attr_set) {
        cudaFuncSetAttribute(gemm_kernel,
                             cudaFuncAttributeMaxDynamicSharedMemorySize, SMEM_SIZE);
        attr_set = true;
    }
    gemm_kernel<<<MTILES * NTILES, 256, SMEM_SIZE>>>(b, out);
}

// round 9
// speedup vs baseline: 1.1139x; 1.0434x over previous
#include <cuda_runtime.h>
#include <cuda_fp16.h>
#include <cstdint>

// ============================================================================
// PiLinear: out = qz(qz(x) @ qz(W)^T + b), qz(v) = round(v/u)*u, u = (pi/2)/256
//
// Exact-integer path: i = round(x/u), j = round(w/u) exact in f16; f16 MMA
// with f32 accumulation computes S = sum(i*j) exactly. Epilogue reconstructs
// round(S*u)*u (+bias, requantize).
//
// R9 = R8 + next-stage cp.async burst spread across micro-steps ks=0..5
// (4 chunks after each MMA block instead of 24 at once), smoothing the
// crossbar/LSU contention that limits tensor-pipe occupancy to 72.9%.
// ============================================================================

#define U_F   0.006135923151542565f   // (pi/2)/256
#define INVU_F 162.97466172610083f    // 512/pi

static constexpr int M_DIM = 8192;
static constexpr int N_DIM = 4096;
static constexpr int K_DIM = 4096;

static constexpr int BM = 128, BN = 256, BK = 128;
static constexpr int KT = K_DIM / BK;                         // 32 k-tiles
static constexpr int A_STAGE_BYTES = BM * BK * 2;             // 32768
static constexpr int B_STAGE_BYTES = BN * BK * 2;             // 65536
static constexpr int STAGE_BYTES = A_STAGE_BYTES + B_STAGE_BYTES;  // 98304
static constexpr int SMEM_SIZE = 2 * STAGE_BYTES;             // 196608

static constexpr int MTILES = M_DIM / BM;   // 64
static constexpr int NTILES = N_DIM / BN;   // 16

// Quantized f16-integer operand copies (scratch; no allocation allowed).
static __device__ __align__(128) __half g_A16[(size_t)M_DIM * K_DIM];
static __device__ __align__(128) __half g_B16[(size_t)N_DIM * K_DIM];

// ----------------------------------------------------------------------------
// PTX helpers
// ----------------------------------------------------------------------------
__device__ __forceinline__ uint32_t smem_u32(const void* p) {
    uint32_t a;
    asm("{ .reg .u64 t; cvta.to.shared.u64 t, %1; cvt.u32.u64 %0, t; }"
        : "=r"(a) : "l"(p));
    return a;
}

#define CP_ASYNC16(dst, src) \
    asm volatile("cp.async.cg.shared.global [%0], [%1], 16;" \
                 :: "r"(dst), "l"(src) : "memory")
#define CP_COMMIT() asm volatile("cp.async.commit_group;" ::: "memory")
#define CP_WAIT0()  asm volatile("cp.async.wait_group 0;"  ::: "memory")

#define LDSM4(r, addr) \
    asm volatile("ldmatrix.sync.aligned.m8n8.x4.shared.b16 {%0,%1,%2,%3}, [%4];" \
                 : "=r"((r)[0]), "=r"((r)[1]), "=r"((r)[2]), "=r"((r)[3]) \
                 : "r"(addr))

#define MMA16816(d, a, b0, b1) \
    asm volatile("mma.sync.aligned.m16n8k16.row.col.f32.f16.f16.f32 " \
                 "{%0,%1,%2,%3}, {%4,%5,%6,%7}, {%8,%9}, {%0,%1,%2,%3};" \
                 : "+f"((d)[0]), "+f"((d)[1]), "+f"((d)[2]), "+f"((d)[3]) \
                 : "r"((a)[0]), "r"((a)[1]), "r"((a)[2]), "r"((a)[3]), \
                   "r"(b0), "r"(b1))

// ----------------------------------------------------------------------------
// Merged quantize-to-f16 kernel (74% DRAM roofline; unchanged).
// ----------------------------------------------------------------------------
static constexpr int XBLKS = (int)(((size_t)M_DIM * K_DIM / 8) / 256);  // 16384
static constexpr int WBLKS = (int)(((size_t)N_DIM * K_DIM / 8) / 256);  // 8192

__global__ void __launch_bounds__(256) quant2_kernel(
    const float* __restrict__ x, __half* __restrict__ a,
    const float* __restrict__ wgt, __half* __restrict__ b) {
    const int bid = blockIdx.x;
    const float* s;
    __half* d;
    size_t base;
    if (bid < XBLKS) { s = x;   d = a; base = (size_t)bid * 2048; }
    else             { s = wgt; d = b; base = (size_t)(bid - XBLKS) * 2048; }
    const size_t i = base + (size_t)threadIdx.x * 8;
    const float4 v0 = *reinterpret_cast<const float4*>(s + i);
    const float4 v1 = *reinterpret_cast<const float4*>(s + i + 4);
    unsigned short h[8];
    h[0] = __half_as_ushort(__float2half_rn(rintf(__fdiv_rn(v0.x, U_F))));
    h[1] = __half_as_ushort(__float2half_rn(rintf(__fdiv_rn(v0.y, U_F))));
    h[2] = __half_as_ushort(__float2half_rn(rintf(__fdiv_rn(v0.z, U_F))));
    h[3] = __half_as_ushort(__float2half_rn(rintf(__fdiv_rn(v0.w, U_F))));
    h[4] = __half_as_ushort(__float2half_rn(rintf(__fdiv_rn(v1.x, U_F))));
    h[5] = __half_as_ushort(__float2half_rn(rintf(__fdiv_rn(v1.y, U_F))));
    h[6] = __half_as_ushort(__float2half_rn(rintf(__fdiv_rn(v1.z, U_F))));
    h[7] = __half_as_ushort(__float2half_rn(rintf(__fdiv_rn(v1.w, U_F))));
    uint4 p;
    p.x = (uint32_t)h[0] | ((uint32_t)h[1] << 16);
    p.y = (uint32_t)h[2] | ((uint32_t)h[3] << 16);
    p.z = (uint32_t)h[4] | ((uint32_t)h[5] << 16);
    p.w = (uint32_t)h[6] | ((uint32_t)h[7] << 16);
    *reinterpret_cast<uint4*>(d + i) = p;
}

// ----------------------------------------------------------------------------
// Partial stage loader: chunk indices 0..7 -> A, 8..23 -> B. Rows are 256B
// (128 halves); 16 slots of 16B per row, swizzle slot ^= (row & 15).
// ----------------------------------------------------------------------------
template <int PART>  // issues chunks [PART*4, PART*4+4)
__device__ __forceinline__ void load_stage_part(uint32_t sbase, int mbase,
                                                int nbase, int kbase, int tid) {
#pragma unroll
    for (int i = PART * 4; i < PART * 4 + 4; i++) {
        const int c = tid + i * 256;
        if (i < 8) {
            const int row = c >> 4, col16 = c & 15;
            const uint32_t dst = sbase + row * 256 + ((col16 ^ (row & 15)) << 4);
            const void* src = g_A16 + (size_t)(mbase + row) * K_DIM + kbase + col16 * 8;
            CP_ASYNC16(dst, src);
        } else {
            const int cb = c - 2048;
            const int row = cb >> 4, col16 = cb & 15;
            const uint32_t dst = sbase + A_STAGE_BYTES + row * 256 + ((col16 ^ (row & 15)) << 4);
            const void* src = g_B16 + (size_t)(nbase + row) * K_DIM + kbase + col16 * 8;
            CP_ASYNC16(dst, src);
        }
    }
}

__device__ __forceinline__ void load_stage_all(uint32_t sbase, int mbase,
                                               int nbase, int kbase, int tid) {
    load_stage_part<0>(sbase, mbase, nbase, kbase, tid);
    load_stage_part<1>(sbase, mbase, nbase, kbase, tid);
    load_stage_part<2>(sbase, mbase, nbase, kbase, tid);
    load_stage_part<3>(sbase, mbase, nbase, kbase, tid);
    load_stage_part<4>(sbase, mbase, nbase, kbase, tid);
    load_stage_part<5>(sbase, mbase, nbase, kbase, tid);
}

// ----------------------------------------------------------------------------
// GEMM: 128x256x128 CTA tile, 2-stage cp.async pipeline, 8 warps (2M x 4N),
// warp tile 64x64 via mma.sync m16n8k16, fused pi-quantize epilogue.
// Next-stage loads spread over micro-steps ks=0..5 (4 chunks each).
// ----------------------------------------------------------------------------
__global__ void __launch_bounds__(256, 1)
gemm_kernel(const float* __restrict__ bias, float* __restrict__ out) {
    extern __shared__ __align__(1024) char smem[];
    const uint32_t sbase = smem_u32(smem);
    const int tid = threadIdx.x;
    const int lane = tid & 31;
    const int w = tid >> 5;

    // banded rasterization: 8 m-tiles x 16 n-tiles per band (128 CTAs/band)
    const int bid = blockIdx.x;
    const int band = bid >> 7;
    const int rem = bid & 127;
    const int mt = band * 8 + (rem & 7);
    const int nt = rem >> 3;
    const int mbase = mt * BM, nbase = nt * BN;

    // prologue: fill stage 0 (k-tile 0)
    load_stage_all(sbase, mbase, nbase, 0, tid);
    CP_COMMIT();

    const int mwarp = w >> 2;        // 0..1 -> 64-row slices
    const int nwarp = w & 3;         // 0..3 -> 64-col slices

    // per-lane invariant smem byte offsets (relative to stage base, 256B rows)
    const int x15a = lane & 15;                              // A row mod 16
    const int x15b = (lane & 7) | (((lane >> 4) & 1) << 3);  // B row mod 16
    uint32_t aoff[4], boff[4];
#pragma unroll
    for (int mi = 0; mi < 4; mi++)
        aoff[mi] = (uint32_t)((mwarp * 64 + mi * 16 + x15a) << 8);
#pragma unroll
    for (int nb = 0; nb < 4; nb++)
        boff[nb] = (uint32_t)(A_STAGE_BYTES + ((nwarp * 64 + nb * 16 + x15b) << 8));
    const int acol = lane >> 4;          // A: +8 halves for lanes 16-31
    const int bcol = (lane >> 3) & 1;    // B: +8 halves pattern

    float acc[4][8][4];
#pragma unroll
    for (int mi = 0; mi < 4; mi++)
#pragma unroll
        for (int nj = 0; nj < 8; nj++)
#pragma unroll
            for (int e = 0; e < 4; e++) acc[mi][nj][e] = 0.f;

    for (int kt = 0; kt < KT; kt++) {
        CP_WAIT0();
        __syncthreads();
        const int cur = kt & 1;
        const uint32_t st = sbase + cur * STAGE_BYTES;
        const uint32_t nst = sbase + (cur ^ 1) * STAGE_BYTES;
        const bool more = (kt + 1 < KT);
        const int nk = (kt + 1) * BK;
#pragma unroll
        for (int ks = 0; ks < 8; ks++) {
            uint32_t a[4][4], b[4][4];
#pragma unroll
            for (int nb = 0; nb < 4; nb++)
                LDSM4(b[nb], st + boff[nb] +
                      ((uint32_t)((ks * 2 + bcol) ^ x15b) << 4));
#pragma unroll
            for (int mi = 0; mi < 4; mi++)
                LDSM4(a[mi], st + aoff[mi] +
                      ((uint32_t)((ks * 2 + acol) ^ x15a) << 4));
#pragma unroll
            for (int mi = 0; mi < 4; mi++)
#pragma unroll
                for (int nj = 0; nj < 8; nj++)
                    MMA16816(acc[mi][nj], a[mi],
                             b[nj >> 1][(nj & 1) * 2], b[nj >> 1][(nj & 1) * 2 + 1]);
            // spread next-stage loads: 4 chunks after each of ks = 0..5
            if (more) {
                switch (ks) {
                    case 0: load_stage_part<0>(nst, mbase, nbase, nk, tid); break;
                    case 1: load_stage_part<1>(nst, mbase, nbase, nk, tid); break;
                    case 2: load_stage_part<2>(nst, mbase, nbase, nk, tid); break;
                    case 3: load_stage_part<3>(nst, mbase, nbase, nk, tid); break;
                    case 4: load_stage_part<4>(nst, mbase, nbase, nk, tid); break;
                    case 5: load_stage_part<5>(nst, mbase, nbase, nk, tid);
                            CP_COMMIT(); break;
                    default: break;
                }
            }
        }
    }

    // ---- epilogue: exact S -> qz(S*u) (+bias) -> qz -> GMEM ----
    const int row0 = mbase + mwarp * 64;
    const int col0 = nbase + nwarp * 64;
    const int tr = lane >> 2;
    const int tc = (lane & 3) * 2;

    float bv[16];
#pragma unroll
    for (int nj = 0; nj < 8; nj++) {
        bv[nj * 2]     = __ldg(bias + col0 + nj * 8 + tc);
        bv[nj * 2 + 1] = __ldg(bias + col0 + nj * 8 + tc + 1);
    }

#pragma unroll
    for (int mi = 0; mi < 4; mi++) {
#pragma unroll
        for (int rr = 0; rr < 2; rr++) {
            const int row = row0 + mi * 16 + rr * 8 + tr;
            float* orow = out + (size_t)row * N_DIM + col0;
#pragma unroll
            for (int nj = 0; nj < 8; nj++) {
                const int c = nj * 8 + tc;
                float2 o;
#pragma unroll
                for (int e = 0; e < 2; e++) {
                    const float sv = acc[mi][nj][rr * 2 + e];        // exact int S
                    const float q  = rintf(__fmul_rn(sv, U_F));      // round(S*u)
                    const float cv = __fmul_rn(q, U_F);              // qz(dot)
                    const float tv = cv + bv[nj * 2 + e];            // + bias
                    (&o.x)[e] = __fmul_rn(rintf(__fmul_rn(tv, INVU_F)), U_F);
                }
                *reinterpret_cast<float2*>(orow + c) = o;
            }
        }
    }
}

// ----------------------------------------------------------------------------
// Host launcher (graph-capturable: kernel launches only)
// ----------------------------------------------------------------------------
extern "C" void kernel_launch(void* const* d_in, const int* in_sizes, int n_in,
                              void* d_out, int out_size) {
    const float* x = (const float*)d_in[0];   // [8192, 4096]
    const float* wgt = (const float*)d_in[1]; // [4096, 4096]
    const float* b = (const float*)d_in[2];   // [4096]
    float* out = (float*)d_out;               // [8192, 4096]

    void* a16 = nullptr; void* b16 = nullptr;
    cudaGetSymbolAddress(&a16, g_A16);
    cudaGetSymbolAddress(&b16, g_B16);

    quant2_kernel<<<XBLKS + WBLKS, 256>>>(x, (__half*)a16, wgt, (__half*)b16);

    static bool attr_set = false;
    if (!attr_set) {
        cudaFuncSetAttribute(gemm_kernel,
                             cudaFuncAttributeMaxDynamicSharedMemorySize, SMEM_SIZE);
        attr_set = true;
    }
    gemm_kernel<<<MTILES * NTILES, 256, SMEM_SIZE>>>(b, out);
}

// round 10
// speedup vs baseline: 1.1838x; 1.0628x over previous
#include <cuda_runtime.h>
#include <cuda_fp16.h>
#include <cstdint>

// ============================================================================
// PiLinear: out = qz(qz(x) @ qz(W)^T + b), qz(v) = round(v/u)*u, u = (pi/2)/256
//
// Exact-integer path: i = round(x/u), j = round(w/u) exact in f16; f16 MMA
// with f32 accumulation computes S = sum(i*j) exactly. Epilogue reconstructs
// round(S*u)*u (+bias, requantize).
//
// R10 = R9 + (a) next-stage loads spread over ks=0..3 with commit at ks=3,
// doubling the in-flight margin before the next wait_group 0; (b) loader
// addresses computed by linear pointer increments (affine in chunk index,
// swizzle term per-thread constant) -- fewer ALU ops, fewer registers.
// ============================================================================

#define U_F   0.006135923151542565f   // (pi/2)/256
#define INVU_F 162.97466172610083f    // 512/pi

static constexpr int M_DIM = 8192;
static constexpr int N_DIM = 4096;
static constexpr int K_DIM = 4096;

static constexpr int BM = 128, BN = 256, BK = 128;
static constexpr int KT = K_DIM / BK;                         // 32 k-tiles
static constexpr int A_STAGE_BYTES = BM * BK * 2;             // 32768
static constexpr int B_STAGE_BYTES = BN * BK * 2;             // 65536
static constexpr int STAGE_BYTES = A_STAGE_BYTES + B_STAGE_BYTES;  // 98304
static constexpr int SMEM_SIZE = 2 * STAGE_BYTES;             // 196608

static constexpr int MTILES = M_DIM / BM;   // 64
static constexpr int NTILES = N_DIM / BN;   // 16

// Quantized f16-integer operand copies (scratch; no allocation allowed).
static __device__ __align__(128) __half g_A16[(size_t)M_DIM * K_DIM];
static __device__ __align__(128) __half g_B16[(size_t)N_DIM * K_DIM];

// ----------------------------------------------------------------------------
// PTX helpers
// ----------------------------------------------------------------------------
__device__ __forceinline__ uint32_t smem_u32(const void* p) {
    uint32_t a;
    asm("{ .reg .u64 t; cvta.to.shared.u64 t, %1; cvt.u32.u64 %0, t; }"
        : "=r"(a) : "l"(p));
    return a;
}

#define CP_ASYNC16(dst, src) \
    asm volatile("cp.async.cg.shared.global [%0], [%1], 16;" \
                 :: "r"(dst), "l"(src) : "memory")
#define CP_COMMIT() asm volatile("cp.async.commit_group;" ::: "memory")
#define CP_WAIT0()  asm volatile("cp.async.wait_group 0;"  ::: "memory")

#define LDSM4(r, addr) \
    asm volatile("ldmatrix.sync.aligned.m8n8.x4.shared.b16 {%0,%1,%2,%3}, [%4];" \
                 : "=r"((r)[0]), "=r"((r)[1]), "=r"((r)[2]), "=r"((r)[3]) \
                 : "r"(addr))

#define MMA16816(d, a, b0, b1) \
    asm volatile("mma.sync.aligned.m16n8k16.row.col.f32.f16.f16.f32 " \
                 "{%0,%1,%2,%3}, {%4,%5,%6,%7}, {%8,%9}, {%0,%1,%2,%3};" \
                 : "+f"((d)[0]), "+f"((d)[1]), "+f"((d)[2]), "+f"((d)[3]) \
                 : "r"((a)[0]), "r"((a)[1]), "r"((a)[2]), "r"((a)[3]), \
                   "r"(b0), "r"(b1))

// ----------------------------------------------------------------------------
// Merged quantize-to-f16 kernel (74% DRAM roofline; unchanged).
// ----------------------------------------------------------------------------
static constexpr int XBLKS = (int)(((size_t)M_DIM * K_DIM / 8) / 256);  // 16384
static constexpr int WBLKS = (int)(((size_t)N_DIM * K_DIM / 8) / 256);  // 8192

__global__ void __launch_bounds__(256) quant2_kernel(
    const float* __restrict__ x, __half* __restrict__ a,
    const float* __restrict__ wgt, __half* __restrict__ b) {
    const int bid = blockIdx.x;
    const float* s;
    __half* d;
    size_t base;
    if (bid < XBLKS) { s = x;   d = a; base = (size_t)bid * 2048; }
    else             { s = wgt; d = b; base = (size_t)(bid - XBLKS) * 2048; }
    const size_t i = base + (size_t)threadIdx.x * 8;
    const float4 v0 = *reinterpret_cast<const float4*>(s + i);
    const float4 v1 = *reinterpret_cast<const float4*>(s + i + 4);
    unsigned short h[8];
    h[0] = __half_as_ushort(__float2half_rn(rintf(__fdiv_rn(v0.x, U_F))));
    h[1] = __half_as_ushort(__float2half_rn(rintf(__fdiv_rn(v0.y, U_F))));
    h[2] = __half_as_ushort(__float2half_rn(rintf(__fdiv_rn(v0.z, U_F))));
    h[3] = __half_as_ushort(__float2half_rn(rintf(__fdiv_rn(v0.w, U_F))));
    h[4] = __half_as_ushort(__float2half_rn(rintf(__fdiv_rn(v1.x, U_F))));
    h[5] = __half_as_ushort(__float2half_rn(rintf(__fdiv_rn(v1.y, U_F))));
    h[6] = __half_as_ushort(__float2half_rn(rintf(__fdiv_rn(v1.z, U_F))));
    h[7] = __half_as_ushort(__float2half_rn(rintf(__fdiv_rn(v1.w, U_F))));
    uint4 p;
    p.x = (uint32_t)h[0] | ((uint32_t)h[1] << 16);
    p.y = (uint32_t)h[2] | ((uint32_t)h[3] << 16);
    p.z = (uint32_t)h[4] | ((uint32_t)h[5] << 16);
    p.w = (uint32_t)h[6] | ((uint32_t)h[7] << 16);
    *reinterpret_cast<uint4*>(d + i) = p;
}

// Per-thread chunk strides: chunk i of A covers rows (tid>>4)+16i; source
// steps by 16 rows = 16*K_DIM halves; dst steps by 16 rows * 256B = 4096B.
static constexpr size_t SRC_STEP = (size_t)16 * K_DIM;   // halves
static constexpr uint32_t DST_STEP = 16 * 256;           // bytes

#define LOAD_A(i) CP_ASYNC16(dA + (i) * DST_STEP, srcA + (size_t)(i) * SRC_STEP)
#define LOAD_B(i) CP_ASYNC16(dB + (i) * DST_STEP, srcB + (size_t)(i) * SRC_STEP)

// ----------------------------------------------------------------------------
// GEMM: 128x256x128 CTA tile, 2-stage cp.async pipeline, 8 warps (2M x 4N),
// warp tile 64x64 via mma.sync m16n8k16, fused pi-quantize epilogue.
// Next-stage loads spread over ks=0..3 (6 chunks each), committed at ks=3.
// ----------------------------------------------------------------------------
__global__ void __launch_bounds__(256, 1)
gemm_kernel(const float* __restrict__ bias, float* __restrict__ out) {
    extern __shared__ __align__(1024) char smem[];
    const uint32_t sbase = smem_u32(smem);
    const int tid = threadIdx.x;
    const int lane = tid & 31;
    const int w = tid >> 5;

    // banded rasterization: 8 m-tiles x 16 n-tiles per band (128 CTAs/band)
    const int bid = blockIdx.x;
    const int band = bid >> 7;
    const int rem = bid & 127;
    const int mt = band * 8 + (rem & 7);
    const int nt = rem >> 3;
    const int mbase = mt * BM, nbase = nt * BN;

    // per-thread loader bases (affine addressing; swizzle term constant)
    const uint32_t toff = ((uint32_t)(tid >> 4) << 8) +
                          ((uint32_t)((tid & 15) ^ ((tid >> 4) & 15)) << 4);
    const __half* srcA = g_A16 + (size_t)(mbase + (tid >> 4)) * K_DIM + (tid & 15) * 8;
    const __half* srcB = g_B16 + (size_t)(nbase + (tid >> 4)) * K_DIM + (tid & 15) * 8;

    // prologue: fill stage 0 (k-tile 0)
    {
        const uint32_t dA = sbase + toff;
        const uint32_t dB = sbase + A_STAGE_BYTES + toff;
#pragma unroll
        for (int i = 0; i < 8; i++)  LOAD_A(i);
#pragma unroll
        for (int i = 0; i < 16; i++) LOAD_B(i);
        CP_COMMIT();
        srcA += BK;
        srcB += BK;
    }

    const int mwarp = w >> 2;        // 0..1 -> 64-row slices
    const int nwarp = w & 3;         // 0..3 -> 64-col slices

    // per-lane invariant smem byte offsets (relative to stage base, 256B rows)
    const int x15a = lane & 15;                              // A row mod 16
    const int x15b = (lane & 7) | (((lane >> 4) & 1) << 3);  // B row mod 16
    uint32_t aoff[4], boff[4];
#pragma unroll
    for (int mi = 0; mi < 4; mi++)
        aoff[mi] = (uint32_t)((mwarp * 64 + mi * 16 + x15a) << 8);
#pragma unroll
    for (int nb = 0; nb < 4; nb++)
        boff[nb] = (uint32_t)(A_STAGE_BYTES + ((nwarp * 64 + nb * 16 + x15b) << 8));
    const int acol = lane >> 4;          // A: +8 halves for lanes 16-31
    const int bcol = (lane >> 3) & 1;    // B: +8 halves pattern

    float acc[4][8][4];
#pragma unroll
    for (int mi = 0; mi < 4; mi++)
#pragma unroll
        for (int nj = 0; nj < 8; nj++)
#pragma unroll
            for (int e = 0; e < 4; e++) acc[mi][nj][e] = 0.f;

    for (int kt = 0; kt < KT; kt++) {
        CP_WAIT0();
        __syncthreads();
        const int cur = kt & 1;
        const uint32_t st = sbase + cur * STAGE_BYTES;
        const uint32_t dA = sbase + (cur ^ 1) * STAGE_BYTES + toff;
        const uint32_t dB = dA + A_STAGE_BYTES;
        const bool more = (kt + 1 < KT);
#pragma unroll
        for (int ks = 0; ks < 8; ks++) {
            uint32_t a[4][4], b[4][4];
#pragma unroll
            for (int nb = 0; nb < 4; nb++)
                LDSM4(b[nb], st + boff[nb] +
                      ((uint32_t)((ks * 2 + bcol) ^ x15b) << 4));
#pragma unroll
            for (int mi = 0; mi < 4; mi++)
                LDSM4(a[mi], st + aoff[mi] +
                      ((uint32_t)((ks * 2 + acol) ^ x15a) << 4));
#pragma unroll
            for (int mi = 0; mi < 4; mi++)
#pragma unroll
                for (int nj = 0; nj < 8; nj++)
                    MMA16816(acc[mi][nj], a[mi],
                             b[nj >> 1][(nj & 1) * 2], b[nj >> 1][(nj & 1) * 2 + 1]);
            // spread next-stage loads: 6 chunks after each of ks = 0..3,
            // commit at ks = 3 -> ~4 micro-steps of in-flight margin.
            if (more) {
                switch (ks) {
                    case 0:
                        LOAD_A(0); LOAD_A(1); LOAD_A(2);
                        LOAD_A(3); LOAD_A(4); LOAD_A(5);
                        break;
                    case 1:
                        LOAD_A(6); LOAD_A(7);
                        LOAD_B(0); LOAD_B(1); LOAD_B(2); LOAD_B(3);
                        break;
                    case 2:
                        LOAD_B(4); LOAD_B(5); LOAD_B(6);
                        LOAD_B(7); LOAD_B(8); LOAD_B(9);
                        break;
                    case 3:
                        LOAD_B(10); LOAD_B(11); LOAD_B(12);
                        LOAD_B(13); LOAD_B(14); LOAD_B(15);
                        CP_COMMIT();
                        break;
                    default: break;
                }
            }
        }
        srcA += BK;
        srcB += BK;
    }

    // ---- epilogue: exact S -> qz(S*u) (+bias) -> qz -> GMEM ----
    const int row0 = mbase + mwarp * 64;
    const int col0 = nbase + nwarp * 64;
    const int tr = lane >> 2;
    const int tc = (lane & 3) * 2;

    float bv[16];
#pragma unroll
    for (int nj = 0; nj < 8; nj++) {
        bv[nj * 2]     = __ldg(bias + col0 + nj * 8 + tc);
        bv[nj * 2 + 1] = __ldg(bias + col0 + nj * 8 + tc + 1);
    }

#pragma unroll
    for (int mi = 0; mi < 4; mi++) {
#pragma unroll
        for (int rr = 0; rr < 2; rr++) {
            const int row = row0 + mi * 16 + rr * 8 + tr;
            float* orow = out + (size_t)row * N_DIM + col0;
#pragma unroll
            for (int nj = 0; nj < 8; nj++) {
                const int c = nj * 8 + tc;
                float2 o;
#pragma unroll
                for (int e = 0; e < 2; e++) {
                    const float sv = acc[mi][nj][rr * 2 + e];        // exact int S
                    const float q  = rintf(__fmul_rn(sv, U_F));      // round(S*u)
                    const float cv = __fmul_rn(q, U_F);              // qz(dot)
                    const float tv = cv + bv[nj * 2 + e];            // + bias
                    (&o.x)[e] = __fmul_rn(rintf(__fmul_rn(tv, INVU_F)), U_F);
                }
                *reinterpret_cast<float2*>(orow + c) = o;
            }
        }
    }
}

// ----------------------------------------------------------------------------
// Host launcher (graph-capturable: kernel launches only)
// ----------------------------------------------------------------------------
extern "C" void kernel_launch(void* const* d_in, const int* in_sizes, int n_in,
                              void* d_out, int out_size) {
    const float* x = (const float*)d_in[0];   // [8192, 4096]
    const float* wgt = (const float*)d_in[1]; // [4096, 4096]
    const float* b = (const float*)d_in[2];   // [4096]
    float* out = (float*)d_out;               // [8192, 4096]

    void* a16 = nullptr; void* b16 = nullptr;
    cudaGetSymbolAddress(&a16, g_A16);
    cudaGetSymbolAddress(&b16, g_B16);

    quant2_kernel<<<XBLKS + WBLKS, 256>>>(x, (__half*)a16, wgt, (__half*)b16);

    static bool attr_set = false;
    if (!attr_set) {
        cudaFuncSetAttribute(gemm_kernel,
                             cudaFuncAttributeMaxDynamicSharedMemorySize, SMEM_SIZE);
        attr_set = true;
    }
    gemm_kernel<<<MTILES * NTILES, 256, SMEM_SIZE>>>(b, out);
}

// round 11
// speedup vs baseline: 1.1845x; 1.0005x over previous
#include <cuda_runtime.h>
#include <cuda_fp16.h>
#include <cstdint>

// ============================================================================
// PiLinear: out = qz(qz(x) @ qz(W)^T + b), qz(v) = round(v/u)*u, u = (pi/2)/256
//
// Exact-integer path: i = round(x/u), j = round(w/u) exact in f16; f16 MMA
// with f32 accumulation computes S = sum(i*j) exactly. Epilogue reconstructs
// round(S*u)*u (+bias, requantize).
//
// R11 = R10 made persistent: grid = #SMs, each CTA walks tiles bid+k*grid
// with a load cursor running one k-stage ahead ACROSS tile boundaries.
// Epilogues overlap the next tile's first-stage loads; per-wave prologue,
// epilogue and wave-transition bubbles (~4.5% of cycles) collapse.
// ============================================================================

#define U_F   0.006135923151542565f   // (pi/2)/256
#define INVU_F 162.97466172610083f    // 512/pi

static constexpr int M_DIM = 8192;
static constexpr int N_DIM = 4096;
static constexpr int K_DIM = 4096;

static constexpr int BM = 128, BN = 256, BK = 128;
static constexpr int KT = K_DIM / BK;                         // 32 k-tiles
static constexpr int A_STAGE_BYTES = BM * BK * 2;             // 32768
static constexpr int B_STAGE_BYTES = BN * BK * 2;             // 65536
static constexpr int STAGE_BYTES = A_STAGE_BYTES + B_STAGE_BYTES;  // 98304
static constexpr int SMEM_SIZE = 2 * STAGE_BYTES;             // 196608

static constexpr int MTILES = M_DIM / BM;   // 64
static constexpr int NTILES = N_DIM / BN;   // 16
static constexpr int TOTAL_TILES = MTILES * NTILES;  // 1024

// Quantized f16-integer operand copies (scratch; no allocation allowed).
static __device__ __align__(128) __half g_A16[(size_t)M_DIM * K_DIM];
static __device__ __align__(128) __half g_B16[(size_t)N_DIM * K_DIM];

// ----------------------------------------------------------------------------
// PTX helpers
// ----------------------------------------------------------------------------
__device__ __forceinline__ uint32_t smem_u32(const void* p) {
    uint32_t a;
    asm("{ .reg .u64 t; cvta.to.shared.u64 t, %1; cvt.u32.u64 %0, t; }"
        : "=r"(a) : "l"(p));
    return a;
}

#define CP_ASYNC16(dst, src) \
    asm volatile("cp.async.cg.shared.global [%0], [%1], 16;" \
                 :: "r"(dst), "l"(src) : "memory")
#define CP_COMMIT() asm volatile("cp.async.commit_group;" ::: "memory")
#define CP_WAIT0()  asm volatile("cp.async.wait_group 0;"  ::: "memory")

#define LDSM4(r, addr) \
    asm volatile("ldmatrix.sync.aligned.m8n8.x4.shared.b16 {%0,%1,%2,%3}, [%4];" \
                 : "=r"((r)[0]), "=r"((r)[1]), "=r"((r)[2]), "=r"((r)[3]) \
                 : "r"(addr))

#define MMA16816(d, a, b0, b1) \
    asm volatile("mma.sync.aligned.m16n8k16.row.col.f32.f16.f16.f32 " \
                 "{%0,%1,%2,%3}, {%4,%5,%6,%7}, {%8,%9}, {%0,%1,%2,%3};" \
                 : "+f"((d)[0]), "+f"((d)[1]), "+f"((d)[2]), "+f"((d)[3]) \
                 : "r"((a)[0]), "r"((a)[1]), "r"((a)[2]), "r"((a)[3]), \
                   "r"(b0), "r"(b1))

// ----------------------------------------------------------------------------
// Merged quantize-to-f16 kernel (74% DRAM roofline; unchanged).
// ----------------------------------------------------------------------------
static constexpr int XBLKS = (int)(((size_t)M_DIM * K_DIM / 8) / 256);  // 16384
static constexpr int WBLKS = (int)(((size_t)N_DIM * K_DIM / 8) / 256);  // 8192

__global__ void __launch_bounds__(256) quant2_kernel(
    const float* __restrict__ x, __half* __restrict__ a,
    const float* __restrict__ wgt, __half* __restrict__ b) {
    const int bid = blockIdx.x;
    const float* s;
    __half* d;
    size_t base;
    if (bid < XBLKS) { s = x;   d = a; base = (size_t)bid * 2048; }
    else             { s = wgt; d = b; base = (size_t)(bid - XBLKS) * 2048; }
    const size_t i = base + (size_t)threadIdx.x * 8;
    const float4 v0 = *reinterpret_cast<const float4*>(s + i);
    const float4 v1 = *reinterpret_cast<const float4*>(s + i + 4);
    unsigned short h[8];
    h[0] = __half_as_ushort(__float2half_rn(rintf(__fdiv_rn(v0.x, U_F))));
    h[1] = __half_as_ushort(__float2half_rn(rintf(__fdiv_rn(v0.y, U_F))));
    h[2] = __half_as_ushort(__float2half_rn(rintf(__fdiv_rn(v0.z, U_F))));
    h[3] = __half_as_ushort(__float2half_rn(rintf(__fdiv_rn(v0.w, U_F))));
    h[4] = __half_as_ushort(__float2half_rn(rintf(__fdiv_rn(v1.x, U_F))));
    h[5] = __half_as_ushort(__float2half_rn(rintf(__fdiv_rn(v1.y, U_F))));
    h[6] = __half_as_ushort(__float2half_rn(rintf(__fdiv_rn(v1.z, U_F))));
    h[7] = __half_as_ushort(__float2half_rn(rintf(__fdiv_rn(v1.w, U_F))));
    uint4 p;
    p.x = (uint32_t)h[0] | ((uint32_t)h[1] << 16);
    p.y = (uint32_t)h[2] | ((uint32_t)h[3] << 16);
    p.z = (uint32_t)h[4] | ((uint32_t)h[5] << 16);
    p.w = (uint32_t)h[6] | ((uint32_t)h[7] << 16);
    *reinterpret_cast<uint4*>(d + i) = p;
}

// Per-thread chunk strides (256B smem rows, 16 rows per chunk step).
static constexpr size_t SRC_STEP = (size_t)16 * K_DIM;   // halves
static constexpr uint32_t DST_STEP = 16 * 256;           // bytes

#define LOAD_A(i) CP_ASYNC16(dA + (i) * DST_STEP, srcA + (size_t)(i) * SRC_STEP)
#define LOAD_B(i) CP_ASYNC16(dB + (i) * DST_STEP, srcB + (size_t)(i) * SRC_STEP)

// banded rasterization: 8 m-tiles x 16 n-tiles per band (128 tiles/band)
__device__ __forceinline__ void tile_mn(int t, int& mb, int& nb) {
    const int band = t >> 7;
    const int rem = t & 127;
    mb = (band * 8 + (rem & 7)) * BM;
    nb = (rem >> 3) * BN;
}

// ----------------------------------------------------------------------------
// Persistent GEMM: 128x256x128 CTA tile, 2-stage cp.async ring continuous
// across tiles, 8 warps (2M x 4N), warp tile 64x64 mma.sync m16n8k16,
// fused pi-quantize epilogue overlapped with the next tile's loads.
// ----------------------------------------------------------------------------
__global__ void __launch_bounds__(256, 1)
gemm_kernel(const float* __restrict__ bias, float* __restrict__ out) {
    extern __shared__ __align__(1024) char smem[];
    const uint32_t sbase = smem_u32(smem);
    const int tid = threadIdx.x;
    const int lane = tid & 31;
    const int w = tid >> 5;
    const int grid = gridDim.x;

    // per-thread loader constants
    const uint32_t toff = ((uint32_t)(tid >> 4) << 8) +
                          ((uint32_t)((tid & 15) ^ ((tid >> 4) & 15)) << 4);
    const int trow = tid >> 4;
    const int tk8  = (tid & 15) * 8;

    // ---- load cursor: one k-stage ahead, continuous across tiles ----
    int ld_tile = blockIdx.x;
    int ld_k = 0;
    int lmb, lnb;
    tile_mn(ld_tile, lmb, lnb);
    const __half* srcA = g_A16 + (size_t)(lmb + trow) * K_DIM + tk8;
    const __half* srcB = g_B16 + (size_t)(lnb + trow) * K_DIM + tk8;

    // prologue: fill stage 0 with first tile's kt0
    {
        const uint32_t dA = sbase + toff;
        const uint32_t dB = dA + A_STAGE_BYTES;
#pragma unroll
        for (int i = 0; i < 8; i++)  LOAD_A(i);
#pragma unroll
        for (int i = 0; i < 16; i++) LOAD_B(i);
        CP_COMMIT();
    }
    // advance cursor to kt1 of first tile
    ld_k = BK; srcA += BK; srcB += BK;

    const int mwarp = w >> 2;        // 0..1 -> 64-row slices
    const int nwarp = w & 3;         // 0..3 -> 64-col slices

    const int x15a = lane & 15;                              // A row mod 16
    const int x15b = (lane & 7) | (((lane >> 4) & 1) << 3);  // B row mod 16
    uint32_t aoff[4], boff[4];
#pragma unroll
    for (int mi = 0; mi < 4; mi++)
        aoff[mi] = (uint32_t)((mwarp * 64 + mi * 16 + x15a) << 8);
#pragma unroll
    for (int nb = 0; nb < 4; nb++)
        boff[nb] = (uint32_t)(A_STAGE_BYTES + ((nwarp * 64 + nb * 16 + x15b) << 8));
    const int acol = lane >> 4;
    const int bcol = (lane >> 3) & 1;

    const int tr = lane >> 2;
    const int tc = (lane & 3) * 2;

    float acc[4][8][4];
#pragma unroll
    for (int mi = 0; mi < 4; mi++)
#pragma unroll
        for (int nj = 0; nj < 8; nj++)
#pragma unroll
            for (int e = 0; e < 4; e++) acc[mi][nj][e] = 0.f;

    int gk = 0;   // global k counter -> stage parity, continuous across tiles

    for (int tile = blockIdx.x; tile < TOTAL_TILES; tile += grid) {
        int mbase, nbase;
        tile_mn(tile, mbase, nbase);

        for (int kt = 0; kt < KT; kt++) {
            CP_WAIT0();
            __syncthreads();
            const int cur = gk & 1;
            const uint32_t st = sbase + cur * STAGE_BYTES;
            const uint32_t dA = sbase + (cur ^ 1) * STAGE_BYTES + toff;
            const uint32_t dB = dA + A_STAGE_BYTES;
            const bool more = (ld_tile < TOTAL_TILES);
#pragma unroll
            for (int ks = 0; ks < 8; ks++) {
                uint32_t a[4][4], b[4][4];
#pragma unroll
                for (int nb = 0; nb < 4; nb++)
                    LDSM4(b[nb], st + boff[nb] +
                          ((uint32_t)((ks * 2 + bcol) ^ x15b) << 4));
#pragma unroll
                for (int mi = 0; mi < 4; mi++)
                    LDSM4(a[mi], st + aoff[mi] +
                          ((uint32_t)((ks * 2 + acol) ^ x15a) << 4));
#pragma unroll
                for (int mi = 0; mi < 4; mi++)
#pragma unroll
                    for (int nj = 0; nj < 8; nj++)
                        MMA16816(acc[mi][nj], a[mi],
                                 b[nj >> 1][(nj & 1) * 2], b[nj >> 1][(nj & 1) * 2 + 1]);
                // spread next-stage loads over ks=0..3, commit at ks=3
                if (more) {
                    switch (ks) {
                        case 0:
                            LOAD_A(0); LOAD_A(1); LOAD_A(2);
                            LOAD_A(3); LOAD_A(4); LOAD_A(5);
                            break;
                        case 1:
                            LOAD_A(6); LOAD_A(7);
                            LOAD_B(0); LOAD_B(1); LOAD_B(2); LOAD_B(3);
                            break;
                        case 2:
                            LOAD_B(4); LOAD_B(5); LOAD_B(6);
                            LOAD_B(7); LOAD_B(8); LOAD_B(9);
                            break;
                        case 3:
                            LOAD_B(10); LOAD_B(11); LOAD_B(12);
                            LOAD_B(13); LOAD_B(14); LOAD_B(15);
                            CP_COMMIT();
                            break;
                        default: break;
                    }
                }
            }
            gk++;
            // advance load cursor (one k-stage ahead; crosses tile boundary)
            if (more) {
                ld_k += BK;
                if (ld_k == K_DIM) {
                    ld_k = 0;
                    ld_tile += grid;
                    if (ld_tile < TOTAL_TILES) {
                        tile_mn(ld_tile, lmb, lnb);
                        srcA = g_A16 + (size_t)(lmb + trow) * K_DIM + tk8;
                        srcB = g_B16 + (size_t)(lnb + trow) * K_DIM + tk8;
                    }
                } else {
                    srcA += BK;
                    srcB += BK;
                }
            }
        }

        // ---- epilogue (overlaps the next tile's in-flight loads) ----
        const int row0 = mbase + mwarp * 64;
        const int col0 = nbase + nwarp * 64;
        float bv[16];
#pragma unroll
        for (int nj = 0; nj < 8; nj++) {
            bv[nj * 2]     = __ldg(bias + col0 + nj * 8 + tc);
            bv[nj * 2 + 1] = __ldg(bias + col0 + nj * 8 + tc + 1);
        }
#pragma unroll
        for (int mi = 0; mi < 4; mi++) {
#pragma unroll
            for (int rr = 0; rr < 2; rr++) {
                const int row = row0 + mi * 16 + rr * 8 + tr;
                float* orow = out + (size_t)row * N_DIM + col0;
#pragma unroll
                for (int nj = 0; nj < 8; nj++) {
                    const int c = nj * 8 + tc;
                    float2 o;
#pragma unroll
                    for (int e = 0; e < 2; e++) {
                        const float sv = acc[mi][nj][rr * 2 + e];    // exact int S
                        const float q  = rintf(__fmul_rn(sv, U_F)); // round(S*u)
                        const float cv = __fmul_rn(q, U_F);         // qz(dot)
                        const float tv = cv + bv[nj * 2 + e];       // + bias
                        (&o.x)[e] = __fmul_rn(rintf(__fmul_rn(tv, INVU_F)), U_F);
                    }
                    *reinterpret_cast<float2*>(orow + c) = o;
                }
            }
        }
        // reset accumulators for the next tile
#pragma unroll
        for (int mi = 0; mi < 4; mi++)
#pragma unroll
            for (int nj = 0; nj < 8; nj++)
#pragma unroll
                for (int e = 0; e < 4; e++) acc[mi][nj][e] = 0.f;
    }
}

// ----------------------------------------------------------------------------
// Host launcher (graph-capturable: kernel launches only)
// ----------------------------------------------------------------------------
extern "C" void kernel_launch(void* const* d_in, const int* in_sizes, int n_in,
                              void* d_out, int out_size) {
    const float* x = (const float*)d_in[0];   // [8192, 4096]
    const float* wgt = (const float*)d_in[1]; // [4096, 4096]
    const float* b = (const float*)d_in[2];   // [4096]
    float* out = (float*)d_out;               // [8192, 4096]

    void* a16 = nullptr; void* b16 = nullptr;
    cudaGetSymbolAddress(&a16, g_A16);
    cudaGetSymbolAddress(&b16, g_B16);

    quant2_kernel<<<XBLKS + WBLKS, 256>>>(x, (__half*)a16, wgt, (__half*)b16);

    static int sm_count = 0;
    if (sm_count == 0) {
        cudaDeviceGetAttribute(&sm_count, cudaDevAttrMultiProcessorCount, 0);
        if (sm_count <= 0) sm_count = 148;
        cudaFuncSetAttribute(gemm_kernel,
                             cudaFuncAttributeMaxDynamicSharedMemorySize, SMEM_SIZE);
    }
    gemm_kernel<<<sm_count, 256, SMEM_SIZE>>>(b, out);
}